// round 8
// baseline (speedup 1.0000x reference)
#include <cuda_runtime.h>
#include <math.h>
#include <stdint.h>

#define HID 1024
#define NB  4096
#define LOQ (-8.0f)
#define SCALEQ 256.0f
#define FULL 0xFFFFFFFFu

// Tables produced by precompute, consumed by eval.
__device__ float    g_t[HID];
__device__ float4   g_C[HID + 1];     // {A0,B0,A1,B1} per interval
__device__ uint16_t g_B[NB];          // bucket -> lower-bound rank

__device__ __forceinline__ float softplus_fast(float z) {
    return fmaxf(z, 0.0f) + log1pf(__expf(-fabsf(z)));
}
__device__ __forceinline__ float kl_term_f(float mu, float sigma, float inv_ps) {
    float r = sigma * inv_ps;
    float m = mu * inv_ps;
    return 0.5f * (fmaf(r, r, -1.0f) + m * m - 2.0f * __logf(r));
}
// Monotone bucketizer — MUST be bit-identical between build and query.
__device__ __forceinline__ int qidx_raw(float v) {
    return __float2int_rd((v - LOQ) * SCALEQ);
}

struct PreSmem {
    union U {
        struct A {
            float s_t[HID];
            int   s_idx[HID];
            float d0[HID], d1[HID], d2[HID], d3[HID];
        } a;                           // 24 KB, dead after gather
        int cnt[NB];                   // 16 KB, used after gather
    } u;
    float ws[4][32];
    float bw[4][32];
    float kw[32];
    int   swi[32];
    float tot[4];
    float kl;
};

__global__ void __launch_bounds__(HID) precompute_kernel(
    const float* __restrict__ W1_mu, const float* __restrict__ W1_rho,
    const float* __restrict__ b1_mu, const float* __restrict__ b1_rho,
    const float* __restrict__ W2_mu, const float* __restrict__ W2_rho,
    const float* __restrict__ b2_mu, const float* __restrict__ b2_rho,
    const float* __restrict__ eps_W1, const float* __restrict__ eps_b1,
    const float* __restrict__ eps_W2, const float* __restrict__ eps_b2,
    float* __restrict__ kl_out)
{
    __shared__ PreSmem S;
    const int j    = threadIdx.x;
    const int lane = j & 31;
    const int warp = j >> 5;

    // ---- Phase A: perturbed params, breakpoint, deltas, baseline, KL ----
    const float sW1 = softplus_fast(W1_rho[j]);
    const float w   = W1_mu[j] + sW1 * eps_W1[j];
    const float sb1 = softplus_fast(b1_rho[j]);
    const float b   = b1_mu[j] + sb1 * eps_b1[j];
    const float sc0 = softplus_fast(W2_rho[j]);
    const float c0  = W2_mu[j] + sc0 * eps_W2[j];
    const float sc1 = softplus_fast(W2_rho[HID + j]);
    const float c1  = W2_mu[HID + j] + sc1 * eps_W2[HID + j];

    float t, dA0, dB0, dA1, dB1;
    float bA0 = 0.0f, bB0 = 0.0f, bA1 = 0.0f, bB1 = 0.0f;
    if (w > 0.0f) {
        t = -b / w;
        dA0 = c0 * w;  dB0 = c0 * b;  dA1 = c1 * w;  dB1 = c1 * b;
    } else if (w < 0.0f) {
        t = -b / w;
        dA0 = -(c0 * w); dB0 = -(c0 * b); dA1 = -(c1 * w); dB1 = -(c1 * b);
        bA0 = c0 * w; bB0 = c0 * b; bA1 = c1 * w; bB1 = c1 * b;
    } else {
        t = INFINITY;
        dA0 = dB0 = dA1 = dB1 = 0.0f;
        if (b > 0.0f) { bB0 = c0 * b; bB1 = c1 * b; }
    }

    S.u.a.d0[j] = dA0; S.u.a.d1[j] = dB0; S.u.a.d2[j] = dA1; S.u.a.d3[j] = dB1;

    const float INV_PS1 = 0.25f;
    const float INV_PS2 = 32.0f / 2.25f;
    float kl = kl_term_f(W1_mu[j],       sW1, INV_PS1)
             + kl_term_f(b1_mu[j],       sb1, INV_PS1)
             + kl_term_f(W2_mu[j],       sc0, INV_PS2)
             + kl_term_f(W2_mu[HID + j], sc1, INV_PS2);
    if (j < 2) kl += kl_term_f(b2_mu[j], softplus_fast(b2_rho[j]), INV_PS2);

    #pragma unroll
    for (int o = 16; o > 0; o >>= 1) {
        bA0 += __shfl_xor_sync(FULL, bA0, o);
        bB0 += __shfl_xor_sync(FULL, bB0, o);
        bA1 += __shfl_xor_sync(FULL, bA1, o);
        bB1 += __shfl_xor_sync(FULL, bB1, o);
        kl  += __shfl_xor_sync(FULL, kl, o);
    }
    if (lane == 0) {
        S.bw[0][warp] = bA0; S.bw[1][warp] = bB0;
        S.bw[2][warp] = bA1; S.bw[3][warp] = bB1;
        S.kw[warp] = kl;
    }

    // ---- Phase B: bitonic sort (t, idx); shuffles <=16, shared >=32 ----
    float my_t = t;
    int   my_i = j;

    #pragma unroll
    for (int k = 2; k <= 32; k <<= 1) {
        const bool up = ((j & k) == 0);
        #pragma unroll
        for (int stp = k >> 1; stp > 0; stp >>= 1) {
            float o_t = __shfl_xor_sync(FULL, my_t, stp);
            int   o_i = __shfl_xor_sync(FULL, my_i, stp);
            bool lower = ((j & stp) == 0);
            float a = lower ? my_t : o_t;
            float bb = lower ? o_t : my_t;
            if ((a > bb) == up) { my_t = o_t; my_i = o_i; }
        }
    }

    #pragma unroll
    for (int k = 64; k <= HID; k <<= 1) {
        S.u.a.s_t[j] = my_t; S.u.a.s_idx[j] = my_i;
        __syncthreads();
        for (int stp = k >> 1; stp >= 32; stp >>= 1) {
            int ixj = j ^ stp;
            if (ixj > j) {
                bool up = ((j & k) == 0);
                float a = S.u.a.s_t[j], bb = S.u.a.s_t[ixj];
                if ((a > bb) == up) {
                    S.u.a.s_t[j] = bb; S.u.a.s_t[ixj] = a;
                    int ti = S.u.a.s_idx[j]; S.u.a.s_idx[j] = S.u.a.s_idx[ixj]; S.u.a.s_idx[ixj] = ti;
                }
            }
            __syncthreads();
        }
        my_t = S.u.a.s_t[j]; my_i = S.u.a.s_idx[j];
        const bool up = ((j & k) == 0);
        #pragma unroll
        for (int stp = 16; stp > 0; stp >>= 1) {
            float o_t = __shfl_xor_sync(FULL, my_t, stp);
            int   o_i = __shfl_xor_sync(FULL, my_i, stp);
            bool lower = ((j & stp) == 0);
            float a = lower ? my_t : o_t;
            float bb = lower ? o_t : my_t;
            if ((a > bb) == up) { my_t = o_t; my_i = o_i; }
        }
    }

    g_t[j] = my_t;

    // Gather this slot's deltas (phase-A writes fenced by sort barriers)
    float v0 = S.u.a.d0[my_i];
    float v1 = S.u.a.d1[my_i];
    float v2 = S.u.a.d2[my_i];
    float v3 = S.u.a.d3[my_i];

    // Bucket of my breakpoint, clamped to [-1, NB-1] (register only)
    int cl = qidx_raw(my_t);
    if (cl < -1) cl = -1; else if (cl > NB - 1) cl = NB - 1;

    __syncthreads();   // all gathers done; union region now becomes cnt[]

    // ---- Bucket histogram + exclusive scan -> g_B ----
    #pragma unroll
    for (int i = 0; i < NB / HID; i++) S.u.cnt[j + i * HID] = 0;
    const int negcnt = __syncthreads_count(cl < 0);   // barrier: zeroing done
    if (cl >= 0) atomicAdd(&S.u.cnt[cl], 1);
    __syncthreads();                                  // histogram done

    {
        int4 c4 = ((const int4*)S.u.cnt)[j];          // buckets 4j..4j+3
        int tsum = c4.x + c4.y + c4.z + c4.w;
        int incl = tsum;
        #pragma unroll
        for (int o = 1; o < 32; o <<= 1) {
            int u = __shfl_up_sync(FULL, incl, o);
            if (lane >= o) incl += u;
        }
        if (lane == 31) S.swi[warp] = incl;
        __syncthreads();
        if (warp == 0) {
            int v = S.swi[lane];
            #pragma unroll
            for (int o = 1; o < 32; o <<= 1) {
                int u = __shfl_up_sync(FULL, v, o);
                if (lane >= o) v += u;
            }
            S.swi[lane] = v;
        }
        __syncthreads();
        int base = negcnt + ((warp == 0) ? 0 : S.swi[warp - 1]) + (incl - tsum);
        ushort4 o4;
        o4.x = (uint16_t)base;
        o4.y = (uint16_t)(base + c4.x);
        o4.z = (uint16_t)(base + c4.x + c4.y);
        o4.w = (uint16_t)(base + c4.x + c4.y + c4.z);
        ((ushort4*)g_B)[j] = o4;
    }

    // ---- Phase C: 4-channel inclusive warp scan of deltas ----
    #pragma unroll
    for (int o = 1; o < 32; o <<= 1) {
        float u0 = __shfl_up_sync(FULL, v0, o);
        float u1 = __shfl_up_sync(FULL, v1, o);
        float u2 = __shfl_up_sync(FULL, v2, o);
        float u3 = __shfl_up_sync(FULL, v3, o);
        if (lane >= o) { v0 += u0; v1 += u1; v2 += u2; v3 += u3; }
    }
    if (lane == 31) {
        S.ws[0][warp] = v0; S.ws[1][warp] = v1;
        S.ws[2][warp] = v2; S.ws[3][warp] = v3;
    }
    __syncthreads();

    if (warp < 4) {
        float v = S.ws[warp][lane];
        #pragma unroll
        for (int o = 1; o < 32; o <<= 1) {
            float u = __shfl_up_sync(FULL, v, o);
            if (lane >= o) v += u;
        }
        S.ws[warp][lane] = v;
    } else if (warp < 8) {
        float v = S.bw[warp - 4][lane];
        #pragma unroll
        for (int o = 16; o > 0; o >>= 1) v += __shfl_xor_sync(FULL, v, o);
        if (lane == 0) S.tot[warp - 4] = v;
    } else if (warp == 8) {
        float v = S.kw[lane];
        #pragma unroll
        for (int o = 16; o > 0; o >>= 1) v += __shfl_xor_sync(FULL, v, o);
        if (lane == 0) S.kl = v;
    }
    __syncthreads();

    if (j == 0) kl_out[0] = S.kl;

    const float b2v0 = b2_mu[0] + softplus_fast(b2_rho[0]) * eps_b2[0];
    const float b2v1 = b2_mu[1] + softplus_fast(b2_rho[1]) * eps_b2[1];

    const float base0 = S.tot[0];
    const float base1 = S.tot[1] + b2v0;
    const float base2 = S.tot[2];
    const float base3 = S.tot[3] + b2v1;

    const float woff0 = (warp == 0) ? 0.0f : S.ws[0][warp - 1];
    const float woff1 = (warp == 0) ? 0.0f : S.ws[1][warp - 1];
    const float woff2 = (warp == 0) ? 0.0f : S.ws[2][warp - 1];
    const float woff3 = (warp == 0) ? 0.0f : S.ws[3][warp - 1];

    float4 c;
    c.x = base0 + woff0 + v0;
    c.y = base1 + woff1 + v1;
    c.z = base2 + woff2 + v2;
    c.w = base3 + woff3 + v3;
    g_C[j + 1] = c;
    if (j == 0) g_C[0] = make_float4(base0, base1, base2, base3);
}

__global__ void __launch_bounds__(256) eval_kernel(
    const float* __restrict__ x, float* __restrict__ out, int N)
{
    __shared__ float4   sC[HID + 1];
    __shared__ float    st[HID + 1];      // +INF sentinel at [HID]
    __shared__ uint16_t sB[NB];

    const int base = blockIdx.x * 512 + threadIdx.x;

    // Prefetch x before the barrier
    float xv0 = 0.0f, xv1 = 0.0f;
    const bool ok0 = (base < N);
    const bool ok1 = (base + 256 < N);
    if (ok0) xv0 = __ldg(x + base);
    if (ok1) xv1 = __ldg(x + base + 256);

    // Fill tables
    {
        for (int u = threadIdx.x; u < HID + 1; u += 256) sC[u] = g_C[u];
        const float4* gt4 = (const float4*)g_t;
        float4* st4 = (float4*)st;
        for (int u = threadIdx.x; u < HID / 4; u += 256) st4[u] = gt4[u];
        if (threadIdx.x == 0) st[HID] = INFINITY;
        const uint32_t* gb = (const uint32_t*)g_B;
        uint32_t* sb = (uint32_t*)sB;
        for (int u = threadIdx.x; u < NB / 2; u += 256) sb[u] = gb[u];
    }
    __syncthreads();

    #pragma unroll
    for (int e = 0; e < 2; e++) {
        const float xv = e ? xv1 : xv0;
        const bool ok = e ? ok1 : ok0;
        const int  i  = e ? (base + 256) : base;
        if (!ok) continue;

        int q = qidx_raw(xv);
        int m;
        if (q < 0) m = 0;
        else {
            if (q > NB - 1) q = NB - 1;
            m = (int)sB[q];
        }
        while (st[m] <= xv) ++m;       // sentinel bounds the walk

        float4 c = sC[m];
        out[i] = fmaf(c.x, xv, c.y);
        float h = fmaf(c.z, xv, c.w);
        out[N + i] = 1e-5f + softplus_fast(h);
    }
}

extern "C" void kernel_launch(void* const* d_in, const int* in_sizes, int n_in,
                              void* d_out, int out_size) {
    const float* x      = (const float*)d_in[0];
    const float* W1_mu  = (const float*)d_in[1];
    const float* W1_rho = (const float*)d_in[2];
    const float* b1_mu  = (const float*)d_in[3];
    const float* b1_rho = (const float*)d_in[4];
    const float* W2_mu  = (const float*)d_in[5];
    const float* W2_rho = (const float*)d_in[6];
    const float* b2_mu  = (const float*)d_in[7];
    const float* b2_rho = (const float*)d_in[8];
    const float* eps_W1 = (const float*)d_in[9];
    const float* eps_b1 = (const float*)d_in[10];
    const float* eps_W2 = (const float*)d_in[11];
    const float* eps_b2 = (const float*)d_in[12];

    float* out = (float*)d_out;
    const int N = in_sizes[0];

    precompute_kernel<<<1, HID>>>(W1_mu, W1_rho, b1_mu, b1_rho,
                                  W2_mu, W2_rho, b2_mu, b2_rho,
                                  eps_W1, eps_b1, eps_W2, eps_b2,
                                  out + 2 * (size_t)N);

    int blocks = (N + 511) / 512;
    eval_kernel<<<blocks, 256>>>(x, out, N);
}